// round 14
// baseline (speedup 1.0000x reference)
#include <cuda_runtime.h>
#include <math.h>
#include <stdint.h>

#define TT 4096   // tokens (B*S)
#define HH 1024   // hidden
#define II 2048   // intermediate
#define EE 8      // experts
// TOP_K = 2

// -------- scratch (static device arrays: no allocs allowed) --------
// NOTE: these symbols must ONLY be referenced from device code. Passing them as
// host-side kernel arguments yields the HOST SHADOW address (ATS-dereferenceable
// on GB300 -> silent C2C traffic or stale zeros). That was the R11/R13 bug.
__device__ int   g_cnt[EE];
__device__ float g_psum[EE];
__device__ float g_zsum;
__device__ int   g_tok[EE * TT];          // bucket -> token
__device__ int   g_tslot[TT * 2];         // token -> slot (e*TT+pos)
__device__ float g_tw[TT * 2];            // token -> normalized weight
__device__ float g_x32[(size_t)TT * HH];             // x pre-rounded to tf32 bits
__device__ float g_act_sh[(size_t)TT * II];          // shared-expert activations (tf32 bits)
__device__ float g_act_rt[(size_t)EE * TT * II];     // routed activations (tf32 bits)
__device__ float g_out2[(size_t)EE * TT * HH];       // routed down-proj, slot-major
// transposed, tf32-pre-rounded weights [N][K]
__device__ float g_gt[(size_t)EE * II * HH];
__device__ float g_ut[(size_t)EE * II * HH];
__device__ float g_dt[(size_t)EE * HH * II];
__device__ float g_sgt[(size_t)II * HH];
__device__ float g_sut[(size_t)II * HH];
__device__ float g_sdt[(size_t)HH * II];

// -------------------- helpers --------------------
__device__ __forceinline__ uint32_t f2tf(float f) {
    uint32_t o; asm("cvt.rna.tf32.f32 %0, %1;" : "=r"(o) : "f"(f)); return o;
}
__device__ __forceinline__ void ldsm4(uint32_t& r0, uint32_t& r1, uint32_t& r2, uint32_t& r3,
                                      uint32_t addr) {
    asm volatile("ldmatrix.sync.aligned.m8n8.x4.shared.b16 {%0,%1,%2,%3}, [%4];"
                 : "=r"(r0), "=r"(r1), "=r"(r2), "=r"(r3) : "r"(addr));
}
__device__ __forceinline__ void mma_tf32(float* c, const uint32_t* a, uint32_t b0, uint32_t b1) {
    asm volatile("mma.sync.aligned.m16n8k8.row.col.f32.tf32.tf32.f32 "
                 "{%0,%1,%2,%3}, {%4,%5,%6,%7}, {%8,%9}, {%0,%1,%2,%3};"
                 : "+f"(c[0]), "+f"(c[1]), "+f"(c[2]), "+f"(c[3])
                 : "r"(a[0]), "r"(a[1]), "r"(a[2]), "r"(a[3]), "r"(b0), "r"(b1));
}
__device__ __forceinline__ void cp_async16(uint32_t saddr, const void* gptr) {
    asm volatile("cp.async.cg.shared.global [%0], [%1], 16;" :: "r"(saddr), "l"(gptr));
}
__device__ __forceinline__ void cp_commit() { asm volatile("cp.async.commit_group;"); }
template<int N>
__device__ __forceinline__ void cp_wait() { asm volatile("cp.async.wait_group %0;" :: "n"(N)); }

// -------------------- init --------------------
__global__ void k_init() {
    int i = threadIdx.x;
    if (i < EE) { g_cnt[i] = 0; g_psum[i] = 0.f; }
    if (i == 0) g_zsum = 0.f;
}

// -------------------- pre-round x to tf32 bits --------------------
__global__ __launch_bounds__(256) void k_xround(const float* __restrict__ x) {
    size_t i = (size_t)blockIdx.x * 256 + threadIdx.x;
    float4 v = ((const float4*)x)[i];
    ((uint4*)g_x32)[i] = make_uint4(f2tf(v.x), f2tf(v.y), f2tf(v.z), f2tf(v.w));
}

// ------ ONE consolidated transpose+round pass: 27 [K][N] slabs -> [N][K] ------
// dst chosen in DEVICE code (device symbol addresses).
__global__ __launch_bounds__(256) void k_wtall(
    const float* __restrict__ gw, const float* __restrict__ uw, const float* __restrict__ dw,
    const float* __restrict__ sg, const float* __restrict__ su, const float* __restrict__ sd)
{
    const int z = blockIdx.z;
    const float* src; float* dst; int K, N;
    if (z < 8)        { size_t o = (size_t)z * HH * II;        src = gw + o; dst = g_gt + o; K = HH; N = II; }
    else if (z < 16)  { size_t o = (size_t)(z - 8) * HH * II;  src = uw + o; dst = g_ut + o; K = HH; N = II; }
    else if (z < 24)  { size_t o = (size_t)(z - 16) * II * HH; src = dw + o; dst = g_dt + o; K = II; N = HH; }
    else if (z == 24) { src = sg; dst = g_sgt; K = HH; N = II; }
    else if (z == 25) { src = su; dst = g_sut; K = HH; N = II; }
    else              { src = sd; dst = g_sdt; K = II; N = HH; }

    const int ntile = N / 32;
    const int n0 = (blockIdx.x % ntile) * 32;
    const int k0 = (blockIdx.x / ntile) * 32;

    __shared__ float tl[32][33];
    const int tx = threadIdx.x & 31, ty = threadIdx.x >> 5;   // 32 x 8
#pragma unroll
    for (int i = 0; i < 4; i++)
        tl[ty + i * 8][tx] = src[(size_t)(k0 + ty + i * 8) * N + n0 + tx];
    __syncthreads();
#pragma unroll
    for (int i = 0; i < 4; i++) {
        float v = tl[tx][ty + i * 8];
        dst[(size_t)(n0 + ty + i * 8) * K + k0 + tx] = __uint_as_float(f2tf(v));
    }
}

// -------------------- router (full fp32 precision) --------------------
__global__ void k_router(const float* __restrict__ x, const float* __restrict__ rw,
                         float* __restrict__ out) {
    __shared__ float s_p[EE];
    __shared__ float s_z;
    if (threadIdx.x < EE) s_p[threadIdx.x] = 0.f;
    if (threadIdx.x == 0) s_z = 0.f;
    __syncthreads();

    const int warp = threadIdx.x >> 5;
    const int lane = threadIdx.x & 31;
    const int t = blockIdx.x * 4 + warp;

    float acc[EE];
#pragma unroll
    for (int e = 0; e < EE; e++) acc[e] = 0.f;
    const float* xr = x + (size_t)t * HH;
    for (int jj = 0; jj < HH / 32; jj++) {
        int j = jj * 32 + lane;
        float xv = xr[j];
        const float* r = rw + j * EE;
#pragma unroll
        for (int e = 0; e < EE; e++) acc[e] = fmaf(xv, r[e], acc[e]);
    }
#pragma unroll
    for (int e = 0; e < EE; e++) {
#pragma unroll
        for (int o = 16; o > 0; o >>= 1) acc[e] += __shfl_xor_sync(0xffffffffu, acc[e], o);
    }

    if (lane == 0) {
        float* lo = out + (size_t)TT * HH + 2 + (size_t)t * EE;
        float mx = acc[0];
#pragma unroll
        for (int e = 1; e < EE; e++) mx = fmaxf(mx, acc[e]);
        float p[EE];
        float se = 0.f;
#pragma unroll
        for (int e = 0; e < EE; e++) { p[e] = expf(acc[e] - mx); se += p[e]; }
        float lse = logf(se) + mx;
        atomicAdd(&s_z, lse * lse);
        float inv = 1.f / se;
#pragma unroll
        for (int e = 0; e < EE; e++) {
            p[e] *= inv;
            lo[e] = acc[e];
            atomicAdd(&s_p[e], p[e]);
        }
        int i0 = 0;
#pragma unroll
        for (int e = 1; e < EE; e++) if (p[e] > p[i0]) i0 = e;
        int i1 = -1;
#pragma unroll
        for (int e = 0; e < EE; e++) {
            if (e == i0) continue;
            if (i1 < 0 || p[e] > p[i1]) i1 = e;
        }
        float ws = p[i0] + p[i1];
        float w0 = p[i0] / ws, w1 = p[i1] / ws;
        int pos0 = atomicAdd(&g_cnt[i0], 1);
        g_tok[i0 * TT + pos0] = t;
        g_tslot[t * 2 + 0] = i0 * TT + pos0; g_tw[t * 2 + 0] = w0;
        int pos1 = atomicAdd(&g_cnt[i1], 1);
        g_tok[i1 * TT + pos1] = t;
        g_tslot[t * 2 + 1] = i1 * TT + pos1; g_tw[t * 2 + 1] = w1;
    }
    __syncthreads();
    if (threadIdx.x < EE) atomicAdd(&g_psum[threadIdx.x], s_p[threadIdx.x]);
    if (threadIdx.x == 0) atomicAdd(&g_zsum, s_z);
}

// ==================== tf32 GEMM, all-ldsm mainloop (zero LDS/cvt) =============
// 256 threads = 8 warps, BM=128, BK=32, warp tile 64x32 (mt=4, nt=4).
// B held TRANSPOSED [n][k] in smem (pitch 36); tf32 B fragments via non-trans
// ldmatrix.x4 (b0=Bt[gid][tig] == ldsm lane map). Mapping proven bit-exact in R11.
// Weights referenced as DEVICE symbols inside the kernel (the R11/R13 fix).
// MODE 0: BN_out=64, Bt = gate rows 0-63 | up rows 64-127; wb picks matrix;
//         epilogue exchanges gate acc via smem, silu(g)*u -> Act (tf32 bits).
// MODE 1: BN=128, single Bt. z<8 -> g_out2 slot-major; z==8 -> out.
#define AW 36
#define ABUF (128 * AW)
#define BBUF (128 * AW)
#define STAGE (ABUF + BBUF)
#define NSTAGE 3
#define XPITCH 66

template<int MODE>
__global__ __launch_bounds__(256, 2) void k_gemm(float* __restrict__ out)
{
    constexpr int KD = (MODE == 1) ? II : HH;
    constexpr int NK = KD / 32;

    const int e = blockIdx.z;
    const bool sp = (e == EE);
    const int nrows = sp ? TT : g_cnt[e];
    const int m0 = blockIdx.y * 128;
    if (m0 >= nrows) return;
    const int n0 = blockIdx.x * ((MODE == 1) ? 128 : 64);

    // transposed weights [N][K] — device symbol addresses (device-code refs)
    const float* __restrict__ B0;
    const float* __restrict__ B1 = nullptr;
    if (MODE == 0) {
        B0 = sp ? g_sgt : g_gt + (size_t)e * HH * II;
        B1 = sp ? g_sut : g_ut + (size_t)e * HH * II;
    } else {
        B0 = sp ? g_sdt : g_dt + (size_t)e * II * HH;
    }
    float* __restrict__ Act = sp ? g_act_sh : (g_act_rt + (size_t)e * TT * II);

    extern __shared__ uint32_t smem[];
    const uint32_t smem_u32 = (uint32_t)__cvta_generic_to_shared(smem);

    const int tid = threadIdx.x;
    const int lane = tid & 31;
    const int warp = tid >> 5;
    int wb, wm, wn;
    if (MODE == 0) { wb = warp >> 2; wm = warp & 1; wn = (warp >> 1) & 1; }
    else           { wb = 0;         wm = warp & 1; wn = warp >> 1; }
    const int gid = lane >> 2;
    const int tig = lane & 3;

    // A: 128x32 tf32 words = 4 float4/thread
    int asm_off[4];
    const float* aptr[4];
#pragma unroll
    for (int l = 0; l < 4; l++) {
        int gi = l * 256 + tid;
        int arow = gi >> 3;
        int acol = (gi & 7) * 4;
        asm_off[l] = arow * AW + acol;
        int r = m0 + arow;
        if (r >= nrows) r = nrows - 1;
        if (MODE == 1) {
            aptr[l] = Act + (size_t)r * II + acol;
        } else {
            int src = sp ? r : g_tok[e * TT + r];
            aptr[l] = g_x32 + (size_t)src * HH + acol;
        }
    }
    // B staging: transposed rows. MODE0: 64 rows gate + 64 rows up; MODE1: 128 rows.
    int bsm_off[4];
    const float* bptr[4];
    if (MODE == 0) {
#pragma unroll
        for (int l = 0; l < 2; l++) {
            int gi = l * 256 + tid;
            int nloc = gi >> 3;          // 0..63
            int seg = (gi & 7) * 4;      // k word group
            bsm_off[l] = nloc * AW + seg;                // gate rows 0-63
            bsm_off[l + 2] = (64 + nloc) * AW + seg;     // up rows 64-127
            bptr[l] = B0 + (size_t)(n0 + nloc) * KD + seg;
            bptr[l + 2] = B1 + (size_t)(n0 + nloc) * KD + seg;
        }
    } else {
#pragma unroll
        for (int l = 0; l < 4; l++) {
            int gi = l * 256 + tid;
            int nloc = gi >> 3;          // 0..127
            int seg = (gi & 7) * 4;
            bsm_off[l] = nloc * AW + seg;
            bptr[l] = B0 + (size_t)(n0 + nloc) * KD + seg;
        }
    }

    // ldsm A addresses
    uint32_t a_addr[4];
#pragma unroll
    for (int mt = 0; mt < 4; mt++) {
        int r = wm * 64 + mt * 16 + (lane & 15);
        int c = (lane >> 4) * 4;
        a_addr[mt] = smem_u32 + (r * AW + c) * 4;
    }
    // ldsm B addresses (2 per warp; each x4 covers 2 nt groups)
    uint32_t b_addr[2];
#pragma unroll
    for (int q = 0; q < 2; q++) {
        int tt = lane >> 3;
        int row = (MODE == 0 ? wb * 64 : 0) + wn * 32 + q * 16 + ((tt & 2) ? 8 : 0) + (lane & 7);
        int kc = (tt & 1) * 4;
        b_addr[q] = smem_u32 + (ABUF + row * AW + kc) * 4;
    }

    float acc[4][4][4];
#pragma unroll
    for (int mt = 0; mt < 4; mt++)
#pragma unroll
        for (int nt = 0; nt < 4; nt++)
#pragma unroll
            for (int j = 0; j < 4; j++) acc[mt][nt][j] = 0.f;

    auto issue = [&](int kt, int slot) {
        const uint32_t sb = smem_u32 + (uint32_t)slot * STAGE * 4;
        const int k0 = kt * 32;
#pragma unroll
        for (int l = 0; l < 4; l++)
            cp_async16(sb + asm_off[l] * 4, aptr[l] + k0);
#pragma unroll
        for (int l = 0; l < 4; l++)
            cp_async16(sb + (ABUF + bsm_off[l]) * 4, bptr[l] + k0);
    };

#pragma unroll
    for (int s = 0; s < NSTAGE - 1; s++) { issue(s, s); cp_commit(); }

    int slot = 0;
    for (int kt = 0; kt < NK; kt++) {
        cp_wait<NSTAGE - 2>();
        __syncthreads();

        if (kt + NSTAGE - 1 < NK) {
            int ns = kt + NSTAGE - 1;
            issue(ns, ns % NSTAGE);
        }
        cp_commit();

        const uint32_t sbyte = (uint32_t)slot * STAGE * 4;
#pragma unroll
        for (int ks = 0; ks < 4; ks++) {
            uint32_t a[4][4];
#pragma unroll
            for (int mt = 0; mt < 4; mt++)
                ldsm4(a[mt][0], a[mt][1], a[mt][2], a[mt][3],
                      a_addr[mt] + sbyte + ks * 32);
            uint32_t bf[4][2];
#pragma unroll
            for (int q = 0; q < 2; q++) {
                ldsm4(bf[2 * q][0], bf[2 * q][1], bf[2 * q + 1][0], bf[2 * q + 1][1],
                      b_addr[q] + sbyte + ks * 32);
            }
#pragma unroll
            for (int nt = 0; nt < 4; nt++)
#pragma unroll
                for (int mt = 0; mt < 4; mt++)
                    mma_tf32(acc[mt][nt], a[mt], bf[nt][0], bf[nt][1]);
        }
        slot = (slot + 1 == NSTAGE) ? 0 : slot + 1;
    }

    // ---- epilogue ----
    if (MODE == 0) {
        cp_wait<0>();
        __syncthreads();
        float* xch = (float*)smem;
        if (wb == 0) {
#pragma unroll
            for (int mt = 0; mt < 4; mt++)
#pragma unroll
                for (int i = 0; i < 2; i++) {
                    int rlo = wm * 64 + mt * 16 + i * 8 + gid;
#pragma unroll
                    for (int nt = 0; nt < 4; nt++) {
                        int cl = wn * 32 + nt * 8 + tig * 2;
                        xch[rlo * XPITCH + cl]     = acc[mt][nt][i * 2 + 0];
                        xch[rlo * XPITCH + cl + 1] = acc[mt][nt][i * 2 + 1];
                    }
                }
        }
        __syncthreads();
        if (wb == 1) {
#pragma unroll
            for (int mt = 0; mt < 4; mt++)
#pragma unroll
                for (int i = 0; i < 2; i++) {
                    int rlo = wm * 64 + mt * 16 + i * 8 + gid;
                    int rl = m0 + rlo;
                    if (rl >= nrows) continue;
#pragma unroll
                    for (int nt = 0; nt < 4; nt++) {
                        int cl = wn * 32 + nt * 8 + tig * 2;
                        float g0 = xch[rlo * XPITCH + cl];
                        float g1 = xch[rlo * XPITCH + cl + 1];
                        float u0 = acc[mt][nt][i * 2 + 0], u1 = acc[mt][nt][i * 2 + 1];
                        float s0 = u0 * (g0 / (1.f + expf(-g0)));
                        float s1 = u1 * (g1 / (1.f + expf(-g1)));
                        uint2 st = make_uint2(f2tf(s0), f2tf(s1));
                        *(uint2*)(Act + (size_t)rl * II + n0 + cl) = st;
                    }
                }
        }
    } else {
#pragma unroll
        for (int mt = 0; mt < 4; mt++)
#pragma unroll
            for (int i = 0; i < 2; i++) {
                int rl = m0 + wm * 64 + mt * 16 + i * 8 + gid;
                if (rl >= nrows) continue;
#pragma unroll
                for (int nt = 0; nt < 4; nt++) {
                    int col = n0 + wn * 32 + nt * 8 + tig * 2;
                    float2 v = make_float2(acc[mt][nt][i * 2], acc[mt][nt][i * 2 + 1]);
                    if (sp) {
                        *(float2*)(out + (size_t)rl * HH + col) = v;
                    } else {
                        *(float2*)(g_out2 + (size_t)(e * TT + rl) * HH + col) = v;
                    }
                }
            }
    }
}

// -------------------- combine: out[t] += w0*out2[s0] + w1*out2[s1] --------------------
__global__ void k_combine(float* __restrict__ out) {
    const int t = blockIdx.x;
    const int c = threadIdx.x * 4;
    const int s0 = g_tslot[t * 2 + 0], s1 = g_tslot[t * 2 + 1];
    const float w0 = g_tw[t * 2 + 0], w1 = g_tw[t * 2 + 1];
    float4 o = *(const float4*)(out + (size_t)t * HH + c);
    float4 a = *(const float4*)(g_out2 + (size_t)s0 * HH + c);
    float4 b = *(const float4*)(g_out2 + (size_t)s1 * HH + c);
    o.x += w0 * a.x + w1 * b.x;
    o.y += w0 * a.y + w1 * b.y;
    o.z += w0 * a.z + w1 * b.z;
    o.w += w0 * a.w + w1 * b.w;
    *(float4*)(out + (size_t)t * HH + c) = o;
}

// -------------------- finalize losses --------------------
__global__ void k_final(float* __restrict__ out) {
    if (threadIdx.x == 0) {
        float aux = 0.f;
        for (int e = 0; e < EE; e++) aux += (float)g_cnt[e] * g_psum[e];
        aux = aux * (float)EE / ((float)(2) * (float)TT * (float)TT);
        out[(size_t)TT * HH + 0] = aux;
        out[(size_t)TT * HH + 1] = g_zsum / (float)TT;
    }
}

// -------------------- launch --------------------
extern "C" void kernel_launch(void* const* d_in, const int* in_sizes, int n_in,
                              void* d_out, int out_size) {
    const float* x   = (const float*)d_in[0];
    const float* rw  = (const float*)d_in[1];
    const float* gw  = (const float*)d_in[2];
    const float* uw  = (const float*)d_in[3];
    const float* dw  = (const float*)d_in[4];
    const float* sgw = (const float*)d_in[5];
    const float* suw = (const float*)d_in[6];
    const float* sdw = (const float*)d_in[7];
    float* out = (float*)d_out;

    const int smemB = NSTAGE * STAGE * 4;   // 110,592 B
    cudaFuncSetAttribute(k_gemm<0>, cudaFuncAttributeMaxDynamicSharedMemorySize, smemB);
    cudaFuncSetAttribute(k_gemm<1>, cudaFuncAttributeMaxDynamicSharedMemorySize, smemB);

    k_init<<<1, 32>>>();
    k_xround<<<TT * HH / 4 / 256, 256>>>(x);
    // single consolidated transpose+round pass (27 slabs x 2048 tiles)
    k_wtall<<<dim3(2048, 1, 27), 256>>>(gw, uw, dw, sgw, suw, sdw);
    k_router<<<TT / 4, 128>>>(x, rw, out);
    // fused gate+up: act = tf32(silu(X@Wg) * (X@Wu)) — BN_out=64
    k_gemm<0><<<dim3(II / 64, TT / 128, EE + 1), 256, smemB>>>(out);
    // down: BN=128; routed -> g_out2 (slot-major), shared -> out
    k_gemm<1><<<dim3(HH / 128, TT / 128, EE + 1), 256, smemB>>>(out);
    // combine top-2 weighted routed results into out
    k_combine<<<TT, 256>>>(out);
    k_final<<<1, 32>>>(out);
}

// round 15
// speedup vs baseline: 1.5555x; 1.5555x over previous
#include <cuda_runtime.h>
#include <math.h>
#include <stdint.h>

#define TT 4096   // tokens (B*S)
#define HH 1024   // hidden
#define II 2048   // intermediate
#define EE 8      // experts
// TOP_K = 2

// -------- scratch (static device arrays: no allocs allowed) --------
// NOTE: reference these symbols ONLY from device code (host-passing yields the
// ATS host-shadow address on GB300 — the R11/R13 trap).
__device__ int   g_cnt[EE];
__device__ float g_psum[EE];
__device__ float g_zsum;
__device__ int   g_tok[EE * TT];          // bucket -> token
__device__ int   g_tslot[TT * 2];         // token -> slot (e*TT+pos)
__device__ float g_tw[TT * 2];            // token -> normalized weight
__device__ float g_x32[(size_t)TT * HH];             // x pre-rounded to tf32 bits
__device__ float g_act_sh[(size_t)TT * II];          // shared-expert activations (tf32 bits)
__device__ float g_act_rt[(size_t)EE * TT * II];     // routed activations (tf32 bits)
__device__ float g_out2[(size_t)EE * TT * HH];       // routed down-proj, slot-major

// -------------------- helpers --------------------
__device__ __forceinline__ uint32_t f2tf(float f) {
    uint32_t o; asm("cvt.rna.tf32.f32 %0, %1;" : "=r"(o) : "f"(f)); return o;
}
__device__ __forceinline__ uint32_t f2tf_u(uint32_t raw) {
    return f2tf(__uint_as_float(raw));
}
__device__ __forceinline__ void ldsm4(uint32_t& r0, uint32_t& r1, uint32_t& r2, uint32_t& r3,
                                      uint32_t addr) {
    asm volatile("ldmatrix.sync.aligned.m8n8.x4.shared.b16 {%0,%1,%2,%3}, [%4];"
                 : "=r"(r0), "=r"(r1), "=r"(r2), "=r"(r3) : "r"(addr));
}
__device__ __forceinline__ void mma_tf32(float* c, const uint32_t* a, uint32_t b0, uint32_t b1) {
    asm volatile("mma.sync.aligned.m16n8k8.row.col.f32.tf32.tf32.f32 "
                 "{%0,%1,%2,%3}, {%4,%5,%6,%7}, {%8,%9}, {%0,%1,%2,%3};"
                 : "+f"(c[0]), "+f"(c[1]), "+f"(c[2]), "+f"(c[3])
                 : "r"(a[0]), "r"(a[1]), "r"(a[2]), "r"(a[3]), "r"(b0), "r"(b1));
}
__device__ __forceinline__ void cp_async16(uint32_t saddr, const void* gptr) {
    asm volatile("cp.async.cg.shared.global [%0], [%1], 16;" :: "r"(saddr), "l"(gptr));
}
__device__ __forceinline__ void cp_commit() { asm volatile("cp.async.commit_group;"); }
template<int N>
__device__ __forceinline__ void cp_wait() { asm volatile("cp.async.wait_group %0;" :: "n"(N)); }

// -------------------- init --------------------
__global__ void k_init() {
    int i = threadIdx.x;
    if (i < EE) { g_cnt[i] = 0; g_psum[i] = 0.f; }
    if (i == 0) g_zsum = 0.f;
}

// -------------------- pre-round x to tf32 bits --------------------
__global__ __launch_bounds__(256) void k_xround(const float* __restrict__ x) {
    size_t i = (size_t)blockIdx.x * 256 + threadIdx.x;
    float4 v = ((const float4*)x)[i];
    ((uint4*)g_x32)[i] = make_uint4(f2tf(v.x), f2tf(v.y), f2tf(v.z), f2tf(v.w));
}

// -------------------- router (rw staged in smem; 8 tokens/block) --------------
__global__ __launch_bounds__(256) void k_router(const float* __restrict__ x,
                                                const float* __restrict__ rw,
                                                float* __restrict__ out) {
    __shared__ float4 s_rw4[HH * EE / 4];   // 32 KB
    __shared__ float s_p[EE];
    __shared__ float s_z;
    if (threadIdx.x < EE) s_p[threadIdx.x] = 0.f;
    if (threadIdx.x == 0) s_z = 0.f;
    // stage router weights once per block (coalesced)
    const float4* rw4 = (const float4*)rw;
#pragma unroll
    for (int i = 0; i < HH * EE / 4 / 256; i++)
        s_rw4[i * 256 + threadIdx.x] = rw4[i * 256 + threadIdx.x];
    __syncthreads();

    const int warp = threadIdx.x >> 5;
    const int lane = threadIdx.x & 31;
    const int t = blockIdx.x * 8 + warp;

    float acc[EE];
#pragma unroll
    for (int e = 0; e < EE; e++) acc[e] = 0.f;
    const float* xr = x + (size_t)t * HH;
    for (int jj = 0; jj < HH / 32; jj++) {
        int j = jj * 32 + lane;
        float xv = xr[j];
        float4 r0 = s_rw4[j * 2 + 0];
        float4 r1 = s_rw4[j * 2 + 1];
        acc[0] = fmaf(xv, r0.x, acc[0]);
        acc[1] = fmaf(xv, r0.y, acc[1]);
        acc[2] = fmaf(xv, r0.z, acc[2]);
        acc[3] = fmaf(xv, r0.w, acc[3]);
        acc[4] = fmaf(xv, r1.x, acc[4]);
        acc[5] = fmaf(xv, r1.y, acc[5]);
        acc[6] = fmaf(xv, r1.z, acc[6]);
        acc[7] = fmaf(xv, r1.w, acc[7]);
    }
#pragma unroll
    for (int e = 0; e < EE; e++) {
#pragma unroll
        for (int o = 16; o > 0; o >>= 1) acc[e] += __shfl_xor_sync(0xffffffffu, acc[e], o);
    }

    if (lane == 0) {
        float* lo = out + (size_t)TT * HH + 2 + (size_t)t * EE;
        float mx = acc[0];
#pragma unroll
        for (int e = 1; e < EE; e++) mx = fmaxf(mx, acc[e]);
        float p[EE];
        float se = 0.f;
#pragma unroll
        for (int e = 0; e < EE; e++) { p[e] = expf(acc[e] - mx); se += p[e]; }
        float lse = logf(se) + mx;
        atomicAdd(&s_z, lse * lse);
        float inv = 1.f / se;
#pragma unroll
        for (int e = 0; e < EE; e++) {
            p[e] *= inv;
            lo[e] = acc[e];
            atomicAdd(&s_p[e], p[e]);
        }
        int i0 = 0;
#pragma unroll
        for (int e = 1; e < EE; e++) if (p[e] > p[i0]) i0 = e;
        int i1 = -1;
#pragma unroll
        for (int e = 0; e < EE; e++) {
            if (e == i0) continue;
            if (i1 < 0 || p[e] > p[i1]) i1 = e;
        }
        float ws = p[i0] + p[i1];
        float w0 = p[i0] / ws, w1 = p[i1] / ws;
        int pos0 = atomicAdd(&g_cnt[i0], 1);
        g_tok[i0 * TT + pos0] = t;
        g_tslot[t * 2 + 0] = i0 * TT + pos0; g_tw[t * 2 + 0] = w0;
        int pos1 = atomicAdd(&g_cnt[i1], 1);
        g_tok[i1 * TT + pos1] = t;
        g_tslot[t * 2 + 1] = i1 * TT + pos1; g_tw[t * 2 + 1] = w1;
    }
    __syncthreads();
    if (threadIdx.x < EE) atomicAdd(&g_psum[threadIdx.x], s_p[threadIdx.x]);
    if (threadIdx.x == 0) atomicAdd(&g_zsum, s_z);
}

// ==================== tf32 GEMM, 3-stage cp.async, warp tile 64x32 (mt=4) =====
// (R12 kernel, unchanged — best known)
#define AW 36
#define ABUF (128 * AW)
#define NSTAGE 3
#define XPITCH 66

template<int MODE>
__global__ __launch_bounds__(256, 2) void k_gemm(
    const float* __restrict__ ew0, const float* __restrict__ ew1,
    const float* __restrict__ sw0, const float* __restrict__ sw1,
    float* __restrict__ out)
{
    constexpr int KD = (MODE == 1) ? II : HH;
    constexpr int ND = (MODE == 1) ? HH : II;
    constexpr int NK = KD / 32;
    constexpr int BWp  = (MODE == 1) ? 136 : 72;
    constexpr int BBUF = 32 * BWp;
    constexpr int NBm  = (MODE == 1) ? 1 : 2;
    constexpr int STAGE = ABUF + NBm * BBUF;

    const int e = blockIdx.z;
    const bool sp = (e == EE);
    const int nrows = sp ? TT : g_cnt[e];
    const int m0 = blockIdx.y * 128;
    if (m0 >= nrows) return;
    const int n0 = blockIdx.x * ((MODE == 1) ? 128 : 64);

    const float* __restrict__ B0 = sp ? sw0 : ew0 + (size_t)e * KD * ND;
    const float* __restrict__ B1 = (MODE == 0) ? (sp ? sw1 : ew1 + (size_t)e * KD * ND) : nullptr;
    float* __restrict__ Act = sp ? g_act_sh : (g_act_rt + (size_t)e * TT * II);

    extern __shared__ uint32_t smem[];
    const uint32_t smem_u32 = (uint32_t)__cvta_generic_to_shared(smem);

    const int tid = threadIdx.x;
    const int lane = tid & 31;
    const int warp = tid >> 5;
    int wb, wm, wn;
    if (MODE == 0) { wb = warp >> 2; wm = warp & 1; wn = (warp >> 1) & 1; }
    else           { wb = 0;         wm = warp & 1; wn = warp >> 1; }
    const int gid = lane >> 2;
    const int tig = lane & 3;

    // A: 128x32 tf32 words = 4 float4/thread (gathered rows -> 4 pointers)
    int asm_off[4];
    const float* aptr[4];
#pragma unroll
    for (int l = 0; l < 4; l++) {
        int gi = l * 256 + tid;
        int arow = gi >> 3;
        int acol = (gi & 7) * 4;
        asm_off[l] = arow * AW + acol;
        int r = m0 + arow;
        if (r >= nrows) r = nrows - 1;
        if (MODE == 1) {
            aptr[l] = Act + (size_t)r * II + acol;
        } else {
            int src = sp ? r : g_tok[e * TT + r];
            aptr[l] = g_x32 + (size_t)src * HH + acol;
        }
    }
    // B staging bases
    int bsm0;
    const float* bbase0;
    const float* bbase1 = nullptr;
    if (MODE == 0) {
        int bkr = tid >> 4, bn = (tid & 15) * 4;
        bsm0 = bkr * BWp + bn;
        bbase0 = B0 + (size_t)bkr * ND + n0 + bn;
        bbase1 = B1 + (size_t)bkr * ND + n0 + bn;
    } else {
        int bkr = tid >> 5, bn = (tid & 31) * 4;
        bsm0 = bkr * BWp + bn;
        bbase0 = B0 + (size_t)bkr * ND + n0 + bn;
    }

    uint32_t a_addr[4];
#pragma unroll
    for (int mt = 0; mt < 4; mt++) {
        int r = wm * 64 + mt * 16 + (lane & 15);
        int c = (lane >> 4) * 4;
        a_addr[mt] = smem_u32 + (r * AW + c) * 4;
    }

    float acc[4][4][4];
#pragma unroll
    for (int mt = 0; mt < 4; mt++)
#pragma unroll
        for (int nt = 0; nt < 4; nt++)
#pragma unroll
            for (int j = 0; j < 4; j++) acc[mt][nt][j] = 0.f;

    auto issue = [&](int kt, int slot) {
        const uint32_t sb = smem_u32 + (uint32_t)slot * STAGE * 4;
        const int k0 = kt * 32;
#pragma unroll
        for (int l = 0; l < 4; l++)
            cp_async16(sb + asm_off[l] * 4, aptr[l] + k0);
        if (MODE == 0) {
#pragma unroll
            for (int l = 0; l < 2; l++) {
                cp_async16(sb + (ABUF + bsm0 + l * 16 * BWp) * 4,
                           bbase0 + (size_t)(k0 + l * 16) * ND);
                cp_async16(sb + (ABUF + BBUF + bsm0 + l * 16 * BWp) * 4,
                           bbase1 + (size_t)(k0 + l * 16) * ND);
            }
        } else {
#pragma unroll
            for (int l = 0; l < 4; l++)
                cp_async16(sb + (ABUF + bsm0 + l * 8 * BWp) * 4,
                           bbase0 + (size_t)(k0 + l * 8) * ND);
        }
    };

#pragma unroll
    for (int s = 0; s < NSTAGE - 1; s++) { issue(s, s); cp_commit(); }

    int slot = 0;
    for (int kt = 0; kt < NK; kt++) {
        cp_wait<NSTAGE - 2>();
        __syncthreads();

        if (kt + NSTAGE - 1 < NK) {
            int ns = kt + NSTAGE - 1;
            issue(ns, ns % NSTAGE);
        }
        cp_commit();

        const uint32_t sbyte = (uint32_t)slot * STAGE * 4;
        const uint32_t* Bc = smem + slot * STAGE + ABUF + ((MODE == 0 && wb) ? BBUF : 0);

        uint32_t bf[2][4][2];
        {
            const int kk = tig;
#pragma unroll
            for (int nt = 0; nt < 4; nt++) {
                const int nn = wn * 32 + nt * 8 + gid;
                bf[0][nt][0] = f2tf_u(Bc[kk * BWp + nn]);
                bf[0][nt][1] = f2tf_u(Bc[(kk + 4) * BWp + nn]);
            }
        }
#pragma unroll
        for (int ks = 0; ks < 4; ks++) {
            const int p = ks & 1;
            uint32_t a[4][4];
#pragma unroll
            for (int mt = 0; mt < 4; mt++)
                ldsm4(a[mt][0], a[mt][1], a[mt][2], a[mt][3],
                      a_addr[mt] + sbyte + ks * 32);
            if (ks < 3) {
                const int kk = (ks + 1) * 8 + tig;
#pragma unroll
                for (int nt = 0; nt < 4; nt++) {
                    const int nn = wn * 32 + nt * 8 + gid;
                    bf[p ^ 1][nt][0] = f2tf_u(Bc[kk * BWp + nn]);
                    bf[p ^ 1][nt][1] = f2tf_u(Bc[(kk + 4) * BWp + nn]);
                }
            }
#pragma unroll
            for (int nt = 0; nt < 4; nt++)
#pragma unroll
                for (int mt = 0; mt < 4; mt++)
                    mma_tf32(acc[mt][nt], a[mt], bf[p][nt][0], bf[p][nt][1]);
        }
        slot = (slot + 1 == NSTAGE) ? 0 : slot + 1;
    }

    // ---- epilogue ----
    if (MODE == 0) {
        cp_wait<0>();
        __syncthreads();
        float* xch = (float*)smem;
        if (wb == 0) {
#pragma unroll
            for (int mt = 0; mt < 4; mt++)
#pragma unroll
                for (int i = 0; i < 2; i++) {
                    int rlo = wm * 64 + mt * 16 + i * 8 + gid;
#pragma unroll
                    for (int nt = 0; nt < 4; nt++) {
                        int cl = wn * 32 + nt * 8 + tig * 2;
                        xch[rlo * XPITCH + cl]     = acc[mt][nt][i * 2 + 0];
                        xch[rlo * XPITCH + cl + 1] = acc[mt][nt][i * 2 + 1];
                    }
                }
        }
        __syncthreads();
        if (wb == 1) {
#pragma unroll
            for (int mt = 0; mt < 4; mt++)
#pragma unroll
                for (int i = 0; i < 2; i++) {
                    int rlo = wm * 64 + mt * 16 + i * 8 + gid;
                    int rl = m0 + rlo;
                    if (rl >= nrows) continue;
#pragma unroll
                    for (int nt = 0; nt < 4; nt++) {
                        int cl = wn * 32 + nt * 8 + tig * 2;
                        float g0 = xch[rlo * XPITCH + cl];
                        float g1 = xch[rlo * XPITCH + cl + 1];
                        float u0 = acc[mt][nt][i * 2 + 0], u1 = acc[mt][nt][i * 2 + 1];
                        float s0 = u0 * (g0 / (1.f + expf(-g0)));
                        float s1 = u1 * (g1 / (1.f + expf(-g1)));
                        uint2 st = make_uint2(f2tf(s0), f2tf(s1));
                        *(uint2*)(Act + (size_t)rl * II + n0 + cl) = st;
                    }
                }
        }
    } else {
#pragma unroll
        for (int mt = 0; mt < 4; mt++)
#pragma unroll
            for (int i = 0; i < 2; i++) {
                int rl = m0 + wm * 64 + mt * 16 + i * 8 + gid;
                if (rl >= nrows) continue;
#pragma unroll
                for (int nt = 0; nt < 4; nt++) {
                    int col = n0 + wn * 32 + nt * 8 + tig * 2;
                    float2 v = make_float2(acc[mt][nt][i * 2], acc[mt][nt][i * 2 + 1]);
                    if (sp) {
                        *(float2*)(out + (size_t)rl * HH + col) = v;
                    } else {
                        *(float2*)(g_out2 + (size_t)(e * TT + rl) * HH + col) = v;
                    }
                }
            }
    }
}

// -------------------- combine: out[t] += w0*out2[s0] + w1*out2[s1] --------------------
__global__ void k_combine(float* __restrict__ out) {
    const int t = blockIdx.x;
    const int c = threadIdx.x * 4;
    const int s0 = g_tslot[t * 2 + 0], s1 = g_tslot[t * 2 + 1];
    const float w0 = g_tw[t * 2 + 0], w1 = g_tw[t * 2 + 1];
    float4 o = *(const float4*)(out + (size_t)t * HH + c);
    float4 a = *(const float4*)(g_out2 + (size_t)s0 * HH + c);
    float4 b = *(const float4*)(g_out2 + (size_t)s1 * HH + c);
    o.x += w0 * a.x + w1 * b.x;
    o.y += w0 * a.y + w1 * b.y;
    o.z += w0 * a.z + w1 * b.z;
    o.w += w0 * a.w + w1 * b.w;
    *(float4*)(out + (size_t)t * HH + c) = o;
}

// -------------------- finalize losses --------------------
__global__ void k_final(float* __restrict__ out) {
    if (threadIdx.x == 0) {
        float aux = 0.f;
        for (int e = 0; e < EE; e++) aux += (float)g_cnt[e] * g_psum[e];
        aux = aux * (float)EE / ((float)(2) * (float)TT * (float)TT);
        out[(size_t)TT * HH + 0] = aux;
        out[(size_t)TT * HH + 1] = g_zsum / (float)TT;
    }
}

// -------------------- launch --------------------
extern "C" void kernel_launch(void* const* d_in, const int* in_sizes, int n_in,
                              void* d_out, int out_size) {
    const float* x   = (const float*)d_in[0];
    const float* rw  = (const float*)d_in[1];
    const float* gw  = (const float*)d_in[2];
    const float* uw  = (const float*)d_in[3];
    const float* dw  = (const float*)d_in[4];
    const float* sgw = (const float*)d_in[5];
    const float* suw = (const float*)d_in[6];
    const float* sdw = (const float*)d_in[7];
    float* out = (float*)d_out;

    const int smem0 = NSTAGE * (ABUF + 2 * 32 * 72) * 4;    // 110,592 B
    const int smem1 = NSTAGE * (ABUF + 1 * 32 * 136) * 4;   // 107,520 B
    cudaFuncSetAttribute(k_gemm<0>, cudaFuncAttributeMaxDynamicSharedMemorySize, smem0);
    cudaFuncSetAttribute(k_gemm<1>, cudaFuncAttributeMaxDynamicSharedMemorySize, smem1);

    k_init<<<1, 32>>>();
    k_xround<<<TT * HH / 4 / 256, 256>>>(x);
    k_router<<<TT / 8, 256>>>(x, rw, out);
    // fused gate+up: act = tf32(silu(X@Wg) * (X@Wu)) — BN_out=64
    k_gemm<0><<<dim3(II / 64, TT / 128, EE + 1), 256, smem0>>>(gw, uw, sgw, suw, out);
    // down: BN=128; routed -> g_out2 (slot-major), shared -> out
    k_gemm<1><<<dim3(HH / 128, TT / 128, EE + 1), 256, smem1>>>(dw, nullptr, sdw, nullptr, out);
    // combine top-2 weighted routed results into out
    k_combine<<<TT, 256>>>(out);
    k_final<<<1, 32>>>(out);
}